// round 14
// baseline (speedup 1.0000x reference)
#include <cuda_runtime.h>
#include <math.h>

#define BATCH  64
#define LSUB   512
#define SWORDS 512
#define HID    768
#define NC     9
#define NWORDS (BATCH * SWORDS)
#define MGRID  296           // 2 blocks/SM, one wave
#define ROWB   3072          // bytes per subword row
#define HALFB  1536          // half row
#define WSLOT  4608          // 3 rows x 1536 (one half-word)
#define WBUF   (2 * WSLOT)   // 9216 per warp, double buffered
#define DYN_B  (8 * WBUF)    // 73728 per block

typedef unsigned long long u64;

__device__ int   g_ls[NWORDS];        // (start<<2)|len
__device__ int   g_widx[NWORDS];      // compacted valid word ids
__device__ int   g_total;
__device__ int   g_alloc;
__device__ int   g_done0;
__device__ float g_loss;
__device__ int   g_cnt;
__device__ int   g_done;

__device__ __forceinline__ u64 fma2(u64 a, u64 b, u64 c) {
    u64 d; asm("fma.rn.f32x2 %0,%1,%2,%3;" : "=l"(d) : "l"(a), "l"(b), "l"(c)); return d;
}
__device__ __forceinline__ u64 add2(u64 a, u64 b) {
    u64 d; asm("add.rn.f32x2 %0,%1,%2;" : "=l"(d) : "l"(a), "l"(b)); return d;
}
__device__ __forceinline__ float upk_sum(u64 v) {
    float lo, hi; asm("mov.b64 {%0,%1},%2;" : "=f"(lo), "=f"(hi) : "l"(v)); return lo + hi;
}
__device__ __forceinline__ void cpa16(unsigned dst, const void* src) {
    asm volatile("cp.async.cg.shared.global [%0], [%1], 16;" :: "r"(dst), "l"(src));
}
#define CP_COMMIT() asm volatile("cp.async.commit_group;" ::: "memory")
#define CP_WAIT1()  asm volatile("cp.async.wait_group 1;" ::: "memory")

// ---------------------------------------------------------------------------
// Setup (identical to R11): scan -> g_ls, compaction -> g_widx/g_total,
// default preds, self-cleaning counters.
// ---------------------------------------------------------------------------
__global__ void __launch_bounds__(256) setup_kernel(
    const int* __restrict__ ids_lens, const float* __restrict__ W,
    const float* __restrict__ bias, float* __restrict__ out)
{
    __shared__ int s_comb[8];
    __shared__ int s_off;
    const int b = blockIdx.x, tid = threadIdx.x;
    const int lane = tid & 31, warp = tid >> 5;

    int2 lp = ((const int2*)(ids_lens + b * SWORDS))[tid];
    int f0 = (lp.x > 0), f1 = (lp.y > 0);
    int comb = ((lp.x + lp.y) << 16) | (f0 + f1);
    int inc = comb;
#pragma unroll
    for (int off = 1; off < 32; off <<= 1) {
        int n = __shfl_up_sync(0xffffffffu, inc, off);
        if (lane >= off) inc += n;
    }
    int lane_ex = inc - comb;
    if (lane == 31) s_comb[warp] = inc;
    __syncthreads();
    int wbase = 0;
#pragma unroll
    for (int i = 0; i < 8; i++) if (i < warp) wbase += s_comb[i];
    int ex = wbase + lane_ex;
    int st0 = ex >> 16;
    int vx  = ex & 0xffff;

    const int base = b * SWORDS + 2 * tid;
    g_ls[base]     = (st0 << 2) | lp.x;
    g_ls[base + 1] = ((st0 + lp.x) << 2) | lp.y;

    if (tid == 0) {
        int t = 0;
#pragma unroll
        for (int i = 0; i < 8; i++) t += s_comb[i];
        s_off = atomicAdd(&g_alloc, t & 0xffff);
    }
    __syncthreads();
    int pos = s_off + vx;
    if (f0) g_widx[pos]      = base;
    if (f1) g_widx[pos + f0] = base + 1;

    {
        float m = -1e30f; int am = 0;
#pragma unroll
        for (int c = 0; c < NC; c++) { float v = bias[c]; if (v > m) { m = v; am = c; } }
        out[1 + base] = (float)am; out[1 + base + 1] = (float)am;
    }
    if (tid == 0) {
        __threadfence();
        int old = atomicAdd(&g_done0, 1);
        if (old == BATCH - 1) {
            g_total = atomicAdd(&g_alloc, 0);
            atomicExch(&g_alloc, 0);
            atomicExch(&g_done0, 0);
        }
    }
}

// ---------------------------------------------------------------------------
// Main: 296 blocks x 256 threads (16 warps/SM). Each warp owns a private
// double-buffered HALF-WORD slot (2 x 4608B). Task stream = halves of its
// strided word list: stage task t+1 via cp.async (no landing registers),
// wait_group 1, compute task t from shared; finalize on odd tasks.
// ---------------------------------------------------------------------------
__global__ void __launch_bounds__(256, 2) main_kernel(
    const float* __restrict__ x,
    const float* __restrict__ bias,
    const int*   __restrict__ label_ids,
    float*       __restrict__ out)
{
    extern __shared__ char dbuf[];          // 8 warps * 9216
    __shared__ float Ws[NC * HID];          // Ws[c*HID + h]
    __shared__ float sb[NC];
    __shared__ float s_loss;
    __shared__ int   s_cnt;

    const int tid  = threadIdx.x;
    const int lane = tid & 31;
    const int warp = tid >> 5;

    // W transposed into shared (const-div by HID -> shift/mul)
    for (int j = tid; j < NC * HID; j += 256) {
        int c = j / HID;
        int h = j - c * HID;
        Ws[j] = ((const float*)bias == nullptr) ? 0.f : 0.f; // placeholder never taken
    }
    // real fill (separate loop keeps compiler simple)
    __syncthreads();
    if (tid == 0) { s_loss = 0.0f; s_cnt = 0; }

    char* mybuf = dbuf + warp * WBUF;
    const unsigned mybuf_u = (unsigned)__cvta_generic_to_shared(mybuf);

    const int total = g_total;
    const int gw = blockIdx.x * 8 + warp;
    const int nw = MGRID * 8;

    float lloss = 0.0f;
    int   lcnt  = 0;
    const ulonglong2 z2 = make_ulonglong2(0ull, 0ull);

    // ---- staging helper: half 'half' of word (w,ls) into slot si ----
    auto stage = [&](int w, int ls, int half, int si) {
        if (w >= 0) {
            int len = ls & 3, st = ls >> 2, batch = w >> 9;
            const char* src = (const char*)(x + ((size_t)(batch * LSUB + st)) * HID)
                              + half * HALFB + lane * 16;
            unsigned dst = mybuf_u + si * WSLOT + lane * 16;
#pragma unroll
            for (int r = 0; r < 3; r++) {
                if (len > r) {
#pragma unroll
                    for (int ch = 0; ch < 3; ch++)
                        cpa16(dst + r * HALFB + ch * 512, src + r * ROWB + ch * 512);
                }
            }
        }
        CP_COMMIT();
    };

    u64 acc[NC];
#pragma unroll
    for (int c = 0; c < NC; c++) acc[c] = 0ull;

    int nk = 0;
    if (gw < total) nk = (total - gw + nw - 1) / nw;

    if (nk > 0) {
        int cw = g_widx[gw];
        int cls = g_ls[cw];
        int nxw = -1, nxls = 0;
        {
            int i1 = gw + nw;
            if (i1 < total) { nxw = g_widx[i1]; nxls = g_ls[nxw]; }
        }
        stage(cw, cls, 0, 0);                 // group 0

        const int NT = 2 * nk;
#pragma unroll 1
        for (int t = 0; t < NT; t++) {
            // stage task t+1 into slot (t+1)&1
            if ((t & 1) == 0) stage(cw, cls, 1, (t + 1) & 1);
            else              stage(nxw, nxls, 0, (t + 1) & 1);
            CP_WAIT1();                        // task t's copies landed
            __syncwarp();

            // compute task t from slot t&1
            {
                int len  = cls & 3;
                int half = t & 1;
                const char* p = mybuf + (t & 1) * WSLOT;
#pragma unroll
                for (int g = 0; g < 3; g++) {
                    int o = g * 512 + lane * 16;
                    ulonglong2 a0 = (len > 0) ? *(const ulonglong2*)(p + o)             : z2;
                    ulonglong2 a1 = (len > 1) ? *(const ulonglong2*)(p + HALFB + o)     : z2;
                    ulonglong2 a2 = (len > 2) ? *(const ulonglong2*)(p + 2 * HALFB + o) : z2;
                    u64 vl = add2(a0.x, add2(a1.x, a2.x));
                    u64 vh = add2(a0.y, add2(a1.y, a2.y));
                    int hb = half * 384 + g * 128 + lane * 4;
#pragma unroll
                    for (int c = 0; c < NC; c++) {
                        ulonglong2 wc = *(const ulonglong2*)&Ws[c * HID + hb];
                        acc[c] = fma2(vl, wc.x, acc[c]);
                        acc[c] = fma2(vh, wc.y, acc[c]);
                    }
                }
            }

            if (t & 1) {
                // finalize word cw
                int len = cls & 3;
                float r[NC];
#pragma unroll
                for (int c = 0; c < NC; c++) r[c] = upk_sum(acc[c]);
#pragma unroll
                for (int c = 0; c < NC; c++) {
#pragma unroll
                    for (int off = 16; off; off >>= 1)
                        r[c] += __shfl_xor_sync(0xffffffffu, r[c], off);
                }
                if (lane == 0) {
                    float inv = 1.0f / (float)len;
                    float lg[NC];
                    float m = -1e30f; int am = 0;
#pragma unroll
                    for (int c = 0; c < NC; c++) {
                        lg[c] = fmaf(r[c], inv, sb[c]);
                        if (lg[c] > m) { m = lg[c]; am = c; }
                    }
                    out[1 + cw] = (float)am;
                    float sum = 0.0f;
#pragma unroll
                    for (int c = 0; c < NC; c++) sum += __expf(lg[c] - m);
                    int lab = label_ids[cw];
                    lab = lab < 0 ? 0 : (lab > NC - 1 ? NC - 1 : lab);
                    lloss += -(lg[lab] - m - __logf(sum));
                    lcnt  += 1;
                }
#pragma unroll
                for (int c = 0; c < NC; c++) acc[c] = 0ull;

                // shift meta, prefetch word (t>>1)+2
                cw = nxw; cls = nxls;
                int idx = gw + ((t >> 1) + 2) * nw;
                if (idx < total) { nxw = g_widx[idx]; nxls = g_ls[nxw]; }
                else             { nxw = -1; nxls = 0; }
            }
        }
    }

    if (lane == 0 && lcnt > 0) {
        atomicAdd(&s_loss, lloss);
        atomicAdd(&s_cnt, lcnt);
    }
    __syncthreads();

    if (tid == 0) {
        if (s_cnt > 0) {
            atomicAdd(&g_loss, s_loss);
            atomicAdd(&g_cnt, s_cnt);
        }
        __threadfence();
        int old = atomicAdd(&g_done, 1);
        if (old == MGRID - 1) {
            float lv = atomicAdd(&g_loss, 0.0f);
            int   cv = atomicAdd(&g_cnt, 0);
            out[0] = lv / fmaxf((float)cv, 1.0f);
            g_loss = 0.0f; g_cnt = 0;
            atomicExch(&g_done, 0);
        }
    }
}

// W/bias shared fill needs real data: do it in a tiny wrapper kernel-side.
// (We fill Ws/sb at the top of main via a second pass to keep codegen simple.)
__global__ void __launch_bounds__(256, 2) main_kernel_real(
    const float* __restrict__ x,
    const float* __restrict__ W,
    const float* __restrict__ bias,
    const int*   __restrict__ label_ids,
    float*       __restrict__ out);

extern "C" void kernel_launch(void* const* d_in, const int* in_sizes, int n_in,
                              void* d_out, int out_size);

// ---------------------------------------------------------------------------
// Real main kernel (with W fill). The one above is unused; kept minimal.
// ---------------------------------------------------------------------------
__global__ void __launch_bounds__(256, 2) main_kernel_real(
    const float* __restrict__ x,
    const float* __restrict__ W,
    const float* __restrict__ bias,
    const int*   __restrict__ label_ids,
    float*       __restrict__ out)
{
    extern __shared__ char dbuf[];
    __shared__ float Ws[NC * HID];
    __shared__ float sb[NC];
    __shared__ float s_loss;
    __shared__ int   s_cnt;

    const int tid  = threadIdx.x;
    const int lane = tid & 31;
    const int warp = tid >> 5;

    for (int j = tid; j < NC * HID; j += 256) {
        int c = j / HID;
        int h = j - c * HID;
        Ws[j] = W[h * NC + c];
    }
    if (tid < NC) sb[tid] = bias[tid];
    if (tid == 0) { s_loss = 0.0f; s_cnt = 0; }
    __syncthreads();

    char* mybuf = dbuf + warp * WBUF;
    const unsigned mybuf_u = (unsigned)__cvta_generic_to_shared(mybuf);

    const int total = g_total;
    const int gw = blockIdx.x * 8 + warp;
    const int nw = MGRID * 8;

    float lloss = 0.0f;
    int   lcnt  = 0;
    const ulonglong2 z2 = make_ulonglong2(0ull, 0ull);

    auto stage = [&](int w, int ls, int half, int si) {
        if (w >= 0) {
            int len = ls & 3, st = ls >> 2, batch = w >> 9;
            const char* src = (const char*)(x + ((size_t)(batch * LSUB + st)) * HID)
                              + half * HALFB + lane * 16;
            unsigned dst = mybuf_u + si * WSLOT + lane * 16;
#pragma unroll
            for (int r = 0; r < 3; r++) {
                if (len > r) {
#pragma unroll
                    for (int ch = 0; ch < 3; ch++)
                        cpa16(dst + r * HALFB + ch * 512, src + r * ROWB + ch * 512);
                }
            }
        }
        CP_COMMIT();
    };

    u64 acc[NC];
#pragma unroll
    for (int c = 0; c < NC; c++) acc[c] = 0ull;

    int nk = 0;
    if (gw < total) nk = (total - gw + nw - 1) / nw;

    if (nk > 0) {
        int cw = g_widx[gw];
        int cls = g_ls[cw];
        int nxw = -1, nxls = 0;
        {
            int i1 = gw + nw;
            if (i1 < total) { nxw = g_widx[i1]; nxls = g_ls[nxw]; }
        }
        stage(cw, cls, 0, 0);

        const int NT = 2 * nk;
#pragma unroll 1
        for (int t = 0; t < NT; t++) {
            if ((t & 1) == 0) stage(cw, cls, 1, (t + 1) & 1);
            else              stage(nxw, nxls, 0, (t + 1) & 1);
            CP_WAIT1();
            __syncwarp();

            {
                int len  = cls & 3;
                int half = t & 1;
                const char* p = mybuf + (t & 1) * WSLOT;
#pragma unroll
                for (int g = 0; g < 3; g++) {
                    int o = g * 512 + lane * 16;
                    ulonglong2 a0 = (len > 0) ? *(const ulonglong2*)(p + o)             : z2;
                    ulonglong2 a1 = (len > 1) ? *(const ulonglong2*)(p + HALFB + o)     : z2;
                    ulonglong2 a2 = (len > 2) ? *(const ulonglong2*)(p + 2 * HALFB + o) : z2;
                    u64 vl = add2(a0.x, add2(a1.x, a2.x));
                    u64 vh = add2(a0.y, add2(a1.y, a2.y));
                    int hb = half * 384 + g * 128 + lane * 4;
#pragma unroll
                    for (int c = 0; c < NC; c++) {
                        ulonglong2 wc = *(const ulonglong2*)&Ws[c * HID + hb];
                        acc[c] = fma2(vl, wc.x, acc[c]);
                        acc[c] = fma2(vh, wc.y, acc[c]);
                    }
                }
            }

            if (t & 1) {
                int len = cls & 3;
                float r[NC];
#pragma unroll
                for (int c = 0; c < NC; c++) r[c] = upk_sum(acc[c]);
#pragma unroll
                for (int c = 0; c < NC; c++) {
#pragma unroll
                    for (int off = 16; off; off >>= 1)
                        r[c] += __shfl_xor_sync(0xffffffffu, r[c], off);
                }
                if (lane == 0) {
                    float inv = 1.0f / (float)len;
                    float lg[NC];
                    float m = -1e30f; int am = 0;
#pragma unroll
                    for (int c = 0; c < NC; c++) {
                        lg[c] = fmaf(r[c], inv, sb[c]);
                        if (lg[c] > m) { m = lg[c]; am = c; }
                    }
                    out[1 + cw] = (float)am;
                    float sum = 0.0f;
#pragma unroll
                    for (int c = 0; c < NC; c++) sum += __expf(lg[c] - m);
                    int lab = label_ids[cw];
                    lab = lab < 0 ? 0 : (lab > NC - 1 ? NC - 1 : lab);
                    lloss += -(lg[lab] - m - __logf(sum));
                    lcnt  += 1;
                }
#pragma unroll
                for (int c = 0; c < NC; c++) acc[c] = 0ull;

                cw = nxw; cls = nxls;
                int idx = gw + ((t >> 1) + 2) * nw;
                if (idx < total) { nxw = g_widx[idx]; nxls = g_ls[nxw]; }
                else             { nxw = -1; nxls = 0; }
            }
        }
    }

    if (lane == 0 && lcnt > 0) {
        atomicAdd(&s_loss, lloss);
        atomicAdd(&s_cnt, lcnt);
    }
    __syncthreads();

    if (tid == 0) {
        if (s_cnt > 0) {
            atomicAdd(&g_loss, s_loss);
            atomicAdd(&g_cnt, s_cnt);
        }
        __threadfence();
        int old = atomicAdd(&g_done, 1);
        if (old == MGRID - 1) {
            float lv = atomicAdd(&g_loss, 0.0f);
            int   cv = atomicAdd(&g_cnt, 0);
            out[0] = lv / fmaxf((float)cv, 1.0f);
            g_loss = 0.0f; g_cnt = 0;
            atomicExch(&g_done, 0);
        }
    }
}

extern "C" void kernel_launch(void* const* d_in, const int* in_sizes, int n_in,
                              void* d_out, int out_size) {
    const float* bert_out  = (const float*)d_in[0];
    const float* W         = (const float*)d_in[1];
    const float* b         = (const float*)d_in[2];
    const int*   ids_lens  = (const int*)d_in[4];
    const int*   label_ids = (const int*)d_in[5];
    float* out = (float*)d_out;

    cudaFuncSetAttribute(main_kernel_real, cudaFuncAttributeMaxDynamicSharedMemorySize, DYN_B);

    setup_kernel<<<BATCH, 256>>>(ids_lens, W, b, out);
    main_kernel_real<<<MGRID, 256, DYN_B>>>(bert_out, W, b, label_ids, out);
}

// round 15
// speedup vs baseline: 1.3161x; 1.3161x over previous
#include <cuda_runtime.h>
#include <math.h>

#define BATCH  64
#define LSUB   512
#define SWORDS 512
#define HID    768
#define NC     9
#define NWORDS (BATCH * SWORDS)
#define MGRID  296          // 2 blocks/SM, one wave
#define PPB    4            // pairs per block (8 warps = 4 warp-pairs)

typedef unsigned long long u64;

__device__ int   g_ls[NWORDS];        // (start<<2)|len
__device__ int   g_widx[NWORDS];      // compacted valid word ids
__device__ int   g_total;
__device__ int   g_alloc;
__device__ int   g_done0;
__device__ float g_loss;
__device__ int   g_cnt;
__device__ int   g_done;

__device__ __forceinline__ u64 fma2(u64 a, u64 b, u64 c) {
    u64 d; asm("fma.rn.f32x2 %0,%1,%2,%3;" : "=l"(d) : "l"(a), "l"(b), "l"(c)); return d;
}
__device__ __forceinline__ u64 add2(u64 a, u64 b) {
    u64 d; asm("add.rn.f32x2 %0,%1,%2;" : "=l"(d) : "l"(a), "l"(b)); return d;
}
__device__ __forceinline__ float upk_sum(u64 v) {
    float lo, hi; asm("mov.b64 {%0,%1},%2;" : "=f"(lo), "=f"(hi) : "l"(v)); return lo + hi;
}

// ---------------------------------------------------------------------------
// Setup (R11, proven): scan -> g_ls, compaction -> g_widx/g_total,
// default preds = argmax(bias), self-cleaning counters.
// ---------------------------------------------------------------------------
__global__ void __launch_bounds__(256) setup_kernel(
    const int* __restrict__ ids_lens, const float* __restrict__ W,
    const float* __restrict__ bias, float* __restrict__ out)
{
    __shared__ int s_comb[8];
    __shared__ int s_off;
    const int b = blockIdx.x, tid = threadIdx.x;
    const int lane = tid & 31, warp = tid >> 5;

    int2 lp = ((const int2*)(ids_lens + b * SWORDS))[tid];
    int f0 = (lp.x > 0), f1 = (lp.y > 0);
    int comb = ((lp.x + lp.y) << 16) | (f0 + f1);
    int inc = comb;
#pragma unroll
    for (int off = 1; off < 32; off <<= 1) {
        int n = __shfl_up_sync(0xffffffffu, inc, off);
        if (lane >= off) inc += n;
    }
    int lane_ex = inc - comb;
    if (lane == 31) s_comb[warp] = inc;
    __syncthreads();
    int wbase = 0;
#pragma unroll
    for (int i = 0; i < 8; i++) if (i < warp) wbase += s_comb[i];
    int ex = wbase + lane_ex;
    int st0 = ex >> 16;
    int vx  = ex & 0xffff;

    const int base = b * SWORDS + 2 * tid;
    g_ls[base]     = (st0 << 2) | lp.x;
    g_ls[base + 1] = ((st0 + lp.x) << 2) | lp.y;

    if (tid == 0) {
        int t = 0;
#pragma unroll
        for (int i = 0; i < 8; i++) t += s_comb[i];
        s_off = atomicAdd(&g_alloc, t & 0xffff);
    }
    __syncthreads();
    int pos = s_off + vx;
    if (f0) g_widx[pos]      = base;
    if (f1) g_widx[pos + f0] = base + 1;

    {
        float m = -1e30f; int am = 0;
#pragma unroll
        for (int c = 0; c < NC; c++) { float v = bias[c]; if (v > m) { m = v; am = c; } }
        out[1 + base] = (float)am; out[1 + base + 1] = (float)am;
    }
    if (tid == 0) {
        __threadfence();
        int old = atomicAdd(&g_done0, 1);
        if (old == BATCH - 1) {
            g_total = atomicAdd(&g_alloc, 0);
            atomicExch(&g_alloc, 0);
            atomicExch(&g_done0, 0);
        }
    }
}

// ---------------------------------------------------------------------------
// Main: 296 blocks x 256 threads. TWO warps per word-pair (split-K over H):
// warp half=0 handles h [0,384), half=1 handles [384,768). Each warp batches
// ALL 18 predicated LDG.128 into r[18] BEFORE any arithmetic (max MLP), then
// 3 fma2 groups. Odd warp ships 18 partials via shared; even warp finishes.
// ---------------------------------------------------------------------------
__global__ void __launch_bounds__(256, 2) main_kernel(
    const float* __restrict__ x,        // [B, L, H]
    const float* __restrict__ W,        // [H, C]
    const float* __restrict__ bias,     // [C]
    const int*   __restrict__ label_ids,
    float*       __restrict__ out)      // out[0]=loss, out[1..]=pred
{
    __shared__ float Ws[NC * HID];      // Ws[c*HID + h]
    __shared__ float sb[NC];
    __shared__ float s_part[PPB][2][2][NC];  // [pair][iterParity][word][class]
    __shared__ float s_loss;
    __shared__ int   s_cnt;

    const int tid  = threadIdx.x;
    const int lane = tid & 31;
    const int warp = tid >> 5;
    const int pr   = warp >> 1;         // warp-pair 0..3
    const int half = warp & 1;          // K-half this warp owns

    for (int j = tid; j < NC * HID; j += 256) {
        int c = j / HID;
        int h = j - c * HID;
        Ws[j] = W[h * NC + c];
    }
    if (tid < NC) sb[tid] = bias[tid];
    if (tid == 0) { s_loss = 0.0f; s_cnt = 0; }
    __syncthreads();

    const int total  = g_total;
    const int npairs = (total + 1) >> 1;
    const int nstride = MGRID * PPB;
    const int2* widx2 = (const int2*)g_widx;

    float lloss = 0.0f;
    int   lcnt  = 0;

    const ulonglong2 z2 = make_ulonglong2(0ull, 0ull);
    const int RS = HID / 4;             // 192 ulonglong2 per row
    const int bid = pr + 1;             // named barrier id 1..4

    int it = 0;
#pragma unroll 1
    for (;;) {
        int p = blockIdx.x * PPB + pr + it * nstride;
        if (p >= npairs) break;
        int par = it & 1;

        int2 wp = widx2[p];
        bool act1 = (2 * p + 1 < total);
        int lsa = g_ls[wp.x];
        int lsb = act1 ? g_ls[wp.y] : 0;
        int len0 = lsa & 3, len1 = lsb & 3;
        int st0  = lsa >> 2, st1 = lsb >> 2;
        int b0 = wp.x >> 9, b1 = wp.y >> 9;

        const ulonglong2* base0 = (const ulonglong2*)(x + ((size_t)(b0 * LSUB + st0)) * HID);
        const ulonglong2* base1 = (const ulonglong2*)(x + ((size_t)(b1 * LSUB + st1)) * HID);

        // ---- LOAD BATCH: all 18 predicated LDG.128 before any math ----
        ulonglong2 r[18];
#pragma unroll
        for (int g = 0; g < 3; g++) {
            int idx = half * 96 + g * 32 + lane;
            r[g*6+0] = (len0 > 0) ? base0[idx]          : z2;
            r[g*6+1] = (len0 > 1) ? base0[idx + RS]     : z2;
            r[g*6+2] = (len0 > 2) ? base0[idx + 2*RS]   : z2;
            r[g*6+3] = (len1 > 0) ? base1[idx]          : z2;
            r[g*6+4] = (len1 > 1) ? base1[idx + RS]     : z2;
            r[g*6+5] = (len1 > 2) ? base1[idx + 2*RS]   : z2;
        }

        // ---- COMPUTE: 3 groups of f32x2 fma against this half of Ws ----
        u64 acc0[NC], acc1[NC];
#pragma unroll
        for (int c = 0; c < NC; c++) { acc0[c] = 0ull; acc1[c] = 0ull; }

#pragma unroll
        for (int g = 0; g < 3; g++) {
            u64 v0l = add2(r[g*6+0].x, add2(r[g*6+1].x, r[g*6+2].x));
            u64 v0h = add2(r[g*6+0].y, add2(r[g*6+1].y, r[g*6+2].y));
            u64 v1l = add2(r[g*6+3].x, add2(r[g*6+4].x, r[g*6+5].x));
            u64 v1h = add2(r[g*6+3].y, add2(r[g*6+4].y, r[g*6+5].y));
            int hb = half * 384 + g * 128 + lane * 4;
#pragma unroll
            for (int c = 0; c < NC; c++) {
                ulonglong2 wc = *(const ulonglong2*)&Ws[c * HID + hb];
                acc0[c] = fma2(v0l, wc.x, acc0[c]);
                acc0[c] = fma2(v0h, wc.y, acc0[c]);
                acc1[c] = fma2(v1l, wc.x, acc1[c]);
                acc1[c] = fma2(v1h, wc.y, acc1[c]);
            }
        }

        // ---- split reduce: word0 -> lanes 0-15, word1 -> lanes 16-31 ----
        float v[NC];
#pragma unroll
        for (int c = 0; c < NC; c++) {
            float s0 = upk_sum(acc0[c]);
            float s1 = upk_sum(acc1[c]);
            float keep = (lane < 16) ? s0 : s1;
            float give = (lane < 16) ? s1 : s0;
            v[c] = keep + __shfl_xor_sync(0xffffffffu, give, 16);
        }
#pragma unroll
        for (int c = 0; c < NC; c++) {
#pragma unroll
            for (int off = 8; off; off >>= 1)
                v[c] += __shfl_xor_sync(0xffffffffu, v[c], off);
        }

        // ---- cross-warp combine: odd warp ships partials, even finishes ----
        if (half == 1) {
            if (lane == 0) {
#pragma unroll
                for (int c = 0; c < NC; c++) s_part[pr][par][0][c] = v[c];
            } else if (lane == 16) {
#pragma unroll
                for (int c = 0; c < NC; c++) s_part[pr][par][1][c] = v[c];
            }
        }
        asm volatile("bar.sync %0, 64;" :: "r"(bid) : "memory");

        if (half == 0 && (lane == 0 || (lane == 16 && act1))) {
            int   w   = (lane == 0) ? wp.x : wp.y;
            int   len = (lane == 0) ? len0 : len1;
            const float* po = s_part[pr][par][(lane == 0) ? 0 : 1];
            float inv = 1.0f / (float)len;
            float lg[NC];
            float m = -1e30f; int am = 0;
#pragma unroll
            for (int c = 0; c < NC; c++) {
                lg[c] = fmaf(v[c] + po[c], inv, sb[c]);
                if (lg[c] > m) { m = lg[c]; am = c; }
            }
            out[1 + w] = (float)am;
            float sum = 0.0f;
#pragma unroll
            for (int c = 0; c < NC; c++) sum += __expf(lg[c] - m);
            int lab = label_ids[w];
            lab = lab < 0 ? 0 : (lab > NC - 1 ? NC - 1 : lab);
            lloss += -(lg[lab] - m - __logf(sum));
            lcnt  += 1;
        }
        it++;
    }

    lloss += __shfl_xor_sync(0xffffffffu, lloss, 16);
    lcnt  += __shfl_xor_sync(0xffffffffu, lcnt,  16);
    if (lane == 0 && lcnt > 0) {
        atomicAdd(&s_loss, lloss);
        atomicAdd(&s_cnt, lcnt);
    }
    __syncthreads();

    if (tid == 0) {
        if (s_cnt > 0) {
            atomicAdd(&g_loss, s_loss);
            atomicAdd(&g_cnt, s_cnt);
        }
        __threadfence();
        int old = atomicAdd(&g_done, 1);
        if (old == MGRID - 1) {
            float lv = atomicAdd(&g_loss, 0.0f);
            int   cv = atomicAdd(&g_cnt, 0);
            out[0] = lv / fmaxf((float)cv, 1.0f);
            g_loss = 0.0f; g_cnt = 0;
            atomicExch(&g_done, 0);
        }
    }
}

extern "C" void kernel_launch(void* const* d_in, const int* in_sizes, int n_in,
                              void* d_out, int out_size) {
    const float* bert_out  = (const float*)d_in[0];
    const float* W         = (const float*)d_in[1];
    const float* b         = (const float*)d_in[2];
    const int*   ids_lens  = (const int*)d_in[4];
    const int*   label_ids = (const int*)d_in[5];
    float* out = (float*)d_out;

    setup_kernel<<<BATCH, 256>>>(ids_lens, W, b, out);
    main_kernel<<<MGRID, 256>>>(bert_out, W, b, label_ids, out);
}